// round 1
// baseline (speedup 1.0000x reference)
#include <cuda_runtime.h>
#include <cstdint>

// Problem constants (from reference): C=1000, N=256, D=512, B=4096
#define CC 1000
#define NN 256
#define DD 512
#define BB 4096

// Scratch (no allocations allowed in kernel_launch)
__device__ int g_last_pos[CC];        // last valid batch pos per class, -1 = none
__device__ int g_src[CC * NN];        // source slot per output row; -1 => batch feature row

// ---------------------------------------------------------------------------
// Kernel 0: init last_pos to -1
__global__ void k_init() {
    int i = blockIdx.x * blockDim.x + threadIdx.x;
    if (i < CC) g_last_pos[i] = -1;
}

// ---------------------------------------------------------------------------
// Kernel 1: per batch item, first-occurrence argmax over targets row, validity
// check, atomicMax of batch position into the class slot. One warp per item.
__global__ void k_select(const int* __restrict__ tgt,
                         const float* __restrict__ bconf,
                         const int* __restrict__ mask,
                         const float* __restrict__ conf) {
    int warp = (blockIdx.x * blockDim.x + threadIdx.x) >> 5;
    int lane = threadIdx.x & 31;
    if (warp >= BB) return;
    if (mask[warp] == 0) return;   // uniform across the warp (same item)

    const int* row = tgt + (long long)warp * CC;
    int bestv = -2147483647 - 1;
    int besti = CC;                // first-occurrence: ties -> smaller index
    for (int j = lane; j < CC; j += 32) {
        int v = row[j];
        if (v > bestv || (v == bestv && j < besti)) { bestv = v; besti = j; }
    }
    #pragma unroll
    for (int off = 16; off; off >>= 1) {
        int ov = __shfl_down_sync(0xffffffffu, bestv, off);
        int oi = __shfl_down_sync(0xffffffffu, besti, off);
        if (ov > bestv || (ov == bestv && oi < besti)) { bestv = ov; besti = oi; }
    }
    if (lane == 0) {
        int t = besti;
        // validity vs ORIGINAL last-slot confidence of the class
        if (bconf[warp] > conf[t * NN + (NN - 1)]) {
            atomicMax(&g_last_pos[t], warp);
        }
    }
}

// ---------------------------------------------------------------------------
// Kernel 2: per class, build conf2 (only slot N-1 replaced when updated),
// stable descending argsort via u64 bitonic sort (desc conf, asc index),
// emit per-output-slot source slot index (post-shift mapping).
__global__ void k_sort(const float* __restrict__ conf,
                       const float* __restrict__ bconf) {
    int c = blockIdx.x;
    int t = threadIdx.x;   // 256 threads, one per slot
    __shared__ unsigned long long key[NN];

    int lp = g_last_pos[c];
    bool updated = (lp >= 0);

    float v = (updated && t == NN - 1) ? bconf[lp] : conf[c * NN + t];
    // order-preserving float->uint (ascending), then invert for descending
    unsigned u = __float_as_uint(v);
    u = (u & 0x80000000u) ? ~u : (u | 0x80000000u);
    unsigned inv = ~u;
    key[t] = ((unsigned long long)inv << 32) | (unsigned)t;
    __syncthreads();

    // ascending bitonic sort of 256 u64 keys
    for (int k = 2; k <= NN; k <<= 1) {
        for (int j = k >> 1; j > 0; j >>= 1) {
            int ixj = t ^ j;
            if (ixj > t) {
                bool up = ((t & k) == 0);
                unsigned long long a = key[t], b = key[ixj];
                if ((a > b) == up) { key[t] = b; key[ixj] = a; }
            }
            __syncthreads();
        }
    }

    int slot = (int)(key[t] & 0xffffffffu);   // pre-shift slot whose conf sorts here
    int s;
    if (updated) s = (slot == NN - 1) ? -1 : slot + 1;  // shifted memory mapping
    else         s = slot;
    g_src[c * NN + t] = s;
}

// ---------------------------------------------------------------------------
// Kernel 3: gather rows. One block per output row (C*N blocks), 128 threads,
// each moves one float4 (128 * 16B = 2KB = D floats).
__global__ void k_gather(const float* __restrict__ mem,
                         const float* __restrict__ bfeat,
                         float* __restrict__ out) {
    long long row = blockIdx.x;        // 0 .. C*N-1
    int c = (int)(row / NN);
    int s = g_src[row];
    const float4* src4;
    if (s < 0) {
        int lp = g_last_pos[c];
        src4 = (const float4*)(bfeat + (long long)lp * DD);
    } else {
        src4 = (const float4*)(mem + ((long long)c * NN + s) * DD);
    }
    float4* dst4 = (float4*)(out + row * (long long)DD);
    dst4[threadIdx.x] = src4[threadIdx.x];
}

// ---------------------------------------------------------------------------
extern "C" void kernel_launch(void* const* d_in, const int* in_sizes, int n_in,
                              void* d_out, int out_size) {
    const float* batch_features    = (const float*)d_in[0];   // [B, D]
    const int*   batch_targets     = (const int*)  d_in[1];   // [B, C] int32
    const float* batch_confidences = (const float*)d_in[2];   // [B]
    const int*   selected_mask     = (const int*)  d_in[3];   // [B]
    const float* memory            = (const float*)d_in[4];   // [C, N, D]
    const float* confidences       = (const float*)d_in[5];   // [C, N]
    float* out = (float*)d_out;                               // [C, N, D]

    k_init<<<(CC + 255) / 256, 256>>>();
    k_select<<<(BB * 32) / 256, 256>>>(batch_targets, batch_confidences,
                                       selected_mask, confidences);
    k_sort<<<CC, NN>>>(confidences, batch_confidences);
    k_gather<<<CC * NN, DD / 4>>>(memory, batch_features, out);
}

// round 2
// speedup vs baseline: 1.1622x; 1.1622x over previous
#include <cuda_runtime.h>
#include <cstdint>

// Problem constants (from reference): C=1000, N=256, D=512, B=4096
#define CC 1000
#define NN 256
#define DD 512
#define BB 4096

#define ROWS_PER_BLOCK 8          // 8 rows * 2KB = 16KB per block
#define GATHER_THREADS 256        // 4 float4 per thread

// Scratch (no allocations allowed in kernel_launch)
__device__ int g_last_pos[CC];    // last valid batch pos per class, -1 = none
__device__ int g_src[CC * NN];    // global source row per output row:
                                  //   >=0 : row index into memory  [C*N)
                                  //   <0  : ~idx = row index into batch_features

// ---------------------------------------------------------------------------
// Kernel 0: init last_pos to -1
__global__ void k_init() {
    int i = blockIdx.x * blockDim.x + threadIdx.x;
    if (i < CC) g_last_pos[i] = -1;
}

// ---------------------------------------------------------------------------
// Kernel 1: per batch item, first-occurrence argmax over targets row, validity
// check, atomicMax of batch position into the class slot. One warp per item.
__global__ void k_select(const int* __restrict__ tgt,
                         const float* __restrict__ bconf,
                         const int* __restrict__ mask,
                         const float* __restrict__ conf) {
    int warp = (blockIdx.x * blockDim.x + threadIdx.x) >> 5;
    int lane = threadIdx.x & 31;
    if (warp >= BB) return;
    if (mask[warp] == 0) return;   // uniform across the warp (same item)

    const int* row = tgt + (long long)warp * CC;
    int bestv = -2147483647 - 1;
    int besti = CC;                // first-occurrence: ties -> smaller index
    for (int j = lane; j < CC; j += 32) {
        int v = row[j];
        if (v > bestv || (v == bestv && j < besti)) { bestv = v; besti = j; }
    }
    #pragma unroll
    for (int off = 16; off; off >>= 1) {
        int ov = __shfl_down_sync(0xffffffffu, bestv, off);
        int oi = __shfl_down_sync(0xffffffffu, besti, off);
        if (ov > bestv || (ov == bestv && oi < besti)) { bestv = ov; besti = oi; }
    }
    if (lane == 0) {
        int t = besti;
        // validity vs ORIGINAL last-slot confidence of the class
        if (bconf[warp] > conf[t * NN + (NN - 1)]) {
            atomicMax(&g_last_pos[t], warp);
        }
    }
}

// ---------------------------------------------------------------------------
// Kernel 2: per class, build conf2 (only slot N-1 replaced when updated),
// stable descending argsort via u64 bitonic sort (desc conf, asc index),
// emit per-output-row GLOBAL source row (post-shift mapping).
__global__ void k_sort(const float* __restrict__ conf,
                       const float* __restrict__ bconf) {
    int c = blockIdx.x;
    int t = threadIdx.x;   // 256 threads, one per slot
    __shared__ unsigned long long key[NN];

    int lp = g_last_pos[c];
    bool updated = (lp >= 0);

    float v = (updated && t == NN - 1) ? bconf[lp] : conf[c * NN + t];
    // order-preserving float->uint (ascending), then invert for descending
    unsigned u = __float_as_uint(v);
    u = (u & 0x80000000u) ? ~u : (u | 0x80000000u);
    unsigned inv = ~u;
    key[t] = ((unsigned long long)inv << 32) | (unsigned)t;
    __syncthreads();

    // ascending bitonic sort of 256 u64 keys
    for (int k = 2; k <= NN; k <<= 1) {
        for (int j = k >> 1; j > 0; j >>= 1) {
            int ixj = t ^ j;
            if (ixj > t) {
                bool up = ((t & k) == 0);
                unsigned long long a = key[t], b = key[ixj];
                if ((a > b) == up) { key[t] = b; key[ixj] = a; }
            }
            __syncthreads();
        }
    }

    int slot = (int)(key[t] & 0xffffffffu);   // pre-shift slot whose conf sorts here
    int src;
    if (updated) {
        if (slot == NN - 1) src = ~lp;                 // new feature from batch
        else                src = c * NN + slot + 1;   // shifted memory row
    } else {
        src = c * NN + slot;
    }
    g_src[c * NN + t] = src;
}

// ---------------------------------------------------------------------------
// Kernel 3: gather rows. One block per 8 output rows, 256 threads, each thread
// moves 4 independent float4s (loads batched before stores -> MLP=4).
// Streaming hints: data is use-once, keep it out of L2's hot set.
__global__ void __launch_bounds__(GATHER_THREADS)
k_gather(const float* __restrict__ mem,
         const float* __restrict__ bfeat,
         float* __restrict__ out) {
    const long long row0 = (long long)blockIdx.x * ROWS_PER_BLOCK;
    const int t = threadIdx.x;

    const float4* src4[4];
    float4 v[4];

    #pragma unroll
    for (int p = 0; p < 4; p++) {
        // element index within the 8-row chunk: 1024 float4 total
        int e = p * GATHER_THREADS + t;
        long long row = row0 + (e >> 7);       // 128 float4 per row
        int col = e & 127;
        int s = g_src[row];
        const float* base = (s >= 0) ? (mem + (long long)s * DD)
                                     : (bfeat + (long long)(~s) * DD);
        src4[p] = (const float4*)base + col;
    }
    #pragma unroll
    for (int p = 0; p < 4; p++) v[p] = __ldcs(src4[p]);

    #pragma unroll
    for (int p = 0; p < 4; p++) {
        int e = p * GATHER_THREADS + t;
        __stcs((float4*)(out) + row0 * (DD / 4) + e, v[p]);
    }
}

// ---------------------------------------------------------------------------
extern "C" void kernel_launch(void* const* d_in, const int* in_sizes, int n_in,
                              void* d_out, int out_size) {
    const float* batch_features    = (const float*)d_in[0];   // [B, D]
    const int*   batch_targets     = (const int*)  d_in[1];   // [B, C] int32
    const float* batch_confidences = (const float*)d_in[2];   // [B]
    const int*   selected_mask     = (const int*)  d_in[3];   // [B]
    const float* memory            = (const float*)d_in[4];   // [C, N, D]
    const float* confidences       = (const float*)d_in[5];   // [C, N]
    float* out = (float*)d_out;                               // [C, N, D]

    k_init<<<(CC + 255) / 256, 256>>>();
    k_select<<<(BB * 32) / 256, 256>>>(batch_targets, batch_confidences,
                                       selected_mask, confidences);
    k_sort<<<CC, NN>>>(confidences, batch_confidences);
    k_gather<<<(CC * NN) / ROWS_PER_BLOCK, GATHER_THREADS>>>(memory, batch_features, out);
}